// round 11
// baseline (speedup 1.0000x reference)
#include <cuda_runtime.h>
#include <cstdint>

// ---------------------------------------------------------------------------
// GatedExpertsEncoder (sm_103a, legacy mma.sync path).
// out = sum_e w[:,e] * act(X @ W_e + b_e), 3 layers, E=8 soft MoE.
// R11: int8 two-digit fixed-point (Ozaki-lite), mma.sync.m16n8k32.s8 (K=32!),
// exact int32 accumulation, 3 products sharing 2 accumulator sets:
//   hi = sum D1*E1 (weight 16384), mid = sum (D1*E0 + D0*E1) (weight 128).
// x ~ sx*(128*D1+D0)/Q per row, w ~ sw*(128*E1+E0)/Q per col, Q=16256.
// fp32 running total in per-thread-private SMEM; fold w_e at expert bounds.
// ---------------------------------------------------------------------------

static constexpr int BATCH = 65536;
static constexpr int DIN   = 512;
static constexpr int DH    = 512;
static constexpr int EXPN  = 8;
static constexpr int KTOT  = EXPN * DIN;   // 4096

static constexpr int BM = 128, BN = 128, BK = 64;
static constexpr int NIT = KTOT / BK;      // 64
static constexpr int NSTAGE = 4;

// stage: A_D1 8K | A_D0 8K | B_E1 8K | B_E0 8K = 32KB (int8, 128 rows x 64B)
static constexpr int OFF_AD0 = 8192;
static constexpr int OFF_BE1 = 16384;
static constexpr int OFF_BE0 = 24576;
static constexpr int STAGE   = 32768;
static constexpr int WSM_OFF = NSTAGE * STAGE;      // 131072 (128*8 fp32)
static constexpr int BSM_OFF = WSM_OFF + 4096;      // 135168 (8*128 fp32)
static constexpr int SXS_OFF = BSM_OFF + 4096;      // 139264 (128 fp32)
static constexpr int SWS_OFF = SXS_OFF + 512;       // 139776 (128 fp32)
static constexpr int TOT_OFF = SWS_OFF + 512;       // 140288 (32*512 fp32)
static constexpr int SMEM_BYTES = TOT_OFF + 65536;  // 205824

// ------------------------------ scratch -----------------------------------
__device__ float g_w [(size_t)BATCH * EXPN];
__device__ float g_h [(size_t)BATCH * DH];
__device__ float g_sx[BATCH];
__device__ __align__(16) int8_t g_xd1[(size_t)BATCH * DIN];
__device__ __align__(16) int8_t g_xd0[(size_t)BATCH * DIN];
__device__ float g_wt [(size_t)3 * DH * KTOT];
__device__ float g_sw [3 * DH];
__device__ __align__(16) int8_t g_wd1[(size_t)3 * DH * KTOT];
__device__ __align__(16) int8_t g_wd0[(size_t)3 * DH * KTOT];

// ------------------------------ helpers -----------------------------------
__device__ __forceinline__ float eluf(float x) { return x > 0.f ? x : expm1f(x); }

__device__ __forceinline__ uint32_t smem_u32(const void* p) {
    uint32_t a;
    asm("{ .reg .u64 t; cvta.to.shared.u64 t, %1; cvt.u32.u64 %0, t; }" : "=r"(a) : "l"(p));
    return a;
}
__device__ __forceinline__ void cp16(uint32_t dst, const void* src) {
    asm volatile("cp.async.cg.shared.global [%0], [%1], 16;" :: "r"(dst), "l"(src) : "memory");
}
__device__ __forceinline__ void ldsm4(uint32_t r[4], uint32_t addr) {
    asm volatile("ldmatrix.sync.aligned.m8n8.x4.shared.b16 {%0,%1,%2,%3}, [%4];"
                 : "=r"(r[0]), "=r"(r[1]), "=r"(r[2]), "=r"(r[3]) : "r"(addr));
}
__device__ __forceinline__ void mma_s8(int c[4], const uint32_t a[4], const uint32_t b[2]) {
    asm("mma.sync.aligned.m16n8k32.row.col.s32.s8.s8.s32 "
        "{%0,%1,%2,%3}, {%4,%5,%6,%7}, {%8,%9}, {%0,%1,%2,%3};\n"
        : "+r"(c[0]), "+r"(c[1]), "+r"(c[2]), "+r"(c[3])
        : "r"(a[0]), "r"(a[1]), "r"(a[2]), "r"(a[3]), "r"(b[0]), "r"(b[1]));
}
__device__ __forceinline__ uint32_t pack4(int a, int b, int c, int d) {
    return (uint32_t)(a & 255) | ((uint32_t)(b & 255) << 8) |
           ((uint32_t)(c & 255) << 16) | ((uint32_t)(d & 255) << 24);
}
// t in [-16256,16256] -> digits d1 in [-127,127], d0 in [-64,63], t = 128*d1+d0
__device__ __forceinline__ void dig2(int t, int& d1, int& d0) {
    d1 = (t + 64) >> 7;
    d0 = t - (d1 << 7);
}

// ---------------------------------------------------------------------------
// Gating MLP (proven since R3).
// ---------------------------------------------------------------------------
__global__ void gating_kernel(const float* __restrict__ z,
                              const void* __restrict__ idx_raw,
                              const float* __restrict__ Wg1, const float* __restrict__ bg1,
                              const float* __restrict__ Wg2, const float* __restrict__ bg2,
                              const float* __restrict__ Wg3, const float* __restrict__ bg3)
{
    __shared__ float bufA[8][128];
    __shared__ float bufB[8][128];
    const int warp = threadIdx.x >> 5;
    const int lane = threadIdx.x & 31;
    const int gwarp = blockIdx.x * 8 + warp;
    const int nwarp = gridDim.x * 8;

    const int* idx32 = (const int*)idx_raw;
    const bool is64 = (idx32[1] == 0);

    for (int row = gwarp; row < BATCH; row += nwarp) {
        const float* zr = z + (size_t)row * DIN;
        for (int k = lane; k < 128; k += 32) {
            int col = is64 ? idx32[2 * k] : idx32[k];
            bufA[warp][k] = zr[col & (DIN - 1)];
        }
        __syncwarp();
        {
            float s0 = bg1[lane * 4 + 0], s1 = bg1[lane * 4 + 1];
            float s2 = bg1[lane * 4 + 2], s3 = bg1[lane * 4 + 3];
            #pragma unroll 8
            for (int k = 0; k < 128; ++k) {
                float xk = bufA[warp][k];
                float4 wv = *(const float4*)(Wg1 + k * 128 + lane * 4);
                s0 = fmaf(xk, wv.x, s0); s1 = fmaf(xk, wv.y, s1);
                s2 = fmaf(xk, wv.z, s2); s3 = fmaf(xk, wv.w, s3);
            }
            bufB[warp][lane * 4 + 0] = eluf(s0);
            bufB[warp][lane * 4 + 1] = eluf(s1);
            bufB[warp][lane * 4 + 2] = eluf(s2);
            bufB[warp][lane * 4 + 3] = eluf(s3);
        }
        __syncwarp();
        {
            float s0 = bg2[lane * 4 + 0], s1 = bg2[lane * 4 + 1];
            float s2 = bg2[lane * 4 + 2], s3 = bg2[lane * 4 + 3];
            #pragma unroll 8
            for (int k = 0; k < 128; ++k) {
                float xk = bufB[warp][k];
                float4 wv = *(const float4*)(Wg2 + k * 128 + lane * 4);
                s0 = fmaf(xk, wv.x, s0); s1 = fmaf(xk, wv.y, s1);
                s2 = fmaf(xk, wv.z, s2); s3 = fmaf(xk, wv.w, s3);
            }
            bufA[warp][lane * 4 + 0] = eluf(s0);
            bufA[warp][lane * 4 + 1] = eluf(s1);
            bufA[warp][lane * 4 + 2] = eluf(s2);
            bufA[warp][lane * 4 + 3] = eluf(s3);
        }
        __syncwarp();
        if (lane < 8) {
            float s = bg3[lane];
            #pragma unroll 8
            for (int k = 0; k < 128; ++k)
                s = fmaf(bufA[warp][k], Wg3[k * 8 + lane], s);
            g_w[(size_t)row * 8 + lane] = s;
        }
        __syncwarp();
    }
}

// ---------------------------------------------------------------------------
// W transpose: W[k=4096][o=512] fp32 -> g_wt[layer][o=512][k=4096] fp32
// ---------------------------------------------------------------------------
__global__ void wtrans_kernel(const float* __restrict__ W, int layer)
{
    __shared__ float T[32][33];
    float* o = g_wt + (size_t)layer * DH * KTOT;
    const int kt = blockIdx.x * 32, ot = blockIdx.y * 32;
    const int tx = threadIdx.x, ty = threadIdx.y;   // 32 x 8
    #pragma unroll
    for (int i = 0; i < 4; ++i)
        T[ty + 8 * i][tx] = W[(size_t)(kt + ty + 8 * i) * DH + ot + tx];
    __syncthreads();
    #pragma unroll
    for (int i = 0; i < 4; ++i)
        o[(size_t)(ot + ty + 8 * i) * KTOT + kt + tx] = T[tx][ty + 8 * i];
}

// ---------------------------------------------------------------------------
// W quantize: per column n, scale = max|.| over K, two int8 digits.
// grid (DH, 3), block 256.
// ---------------------------------------------------------------------------
__global__ void quantw_kernel()
{
    const int n = blockIdx.x, layer = blockIdx.y;
    const size_t base = ((size_t)layer * DH + n) * KTOT;
    const float* wr = g_wt + base;
    __shared__ float red[9];
    const int tid = threadIdx.x, lane = tid & 31, warp = tid >> 5;

    float4 v[4];
    float mx = 0.f;
    #pragma unroll
    for (int j = 0; j < 4; ++j) {
        v[j] = ((const float4*)wr)[tid + 256 * j];
        mx = fmaxf(mx, fmaxf(fmaxf(fabsf(v[j].x), fabsf(v[j].y)),
                             fmaxf(fabsf(v[j].z), fabsf(v[j].w))));
    }
    #pragma unroll
    for (int o = 16; o > 0; o >>= 1) mx = fmaxf(mx, __shfl_xor_sync(~0u, mx, o));
    if (lane == 0) red[warp] = mx;
    __syncthreads();
    if (tid == 0) {
        float s = 1e-30f;
        for (int i = 0; i < 8; ++i) s = fmaxf(s, red[i]);
        red[8] = s;
    }
    __syncthreads();
    const float s = red[8];
    const float inv = 16256.f / s;

    uint32_t* o1 = (uint32_t*)(g_wd1 + base);
    uint32_t* o0 = (uint32_t*)(g_wd0 + base);
    #pragma unroll
    for (int j = 0; j < 4; ++j) {
        int t0 = __float2int_rn(v[j].x * inv), t1 = __float2int_rn(v[j].y * inv);
        int t2 = __float2int_rn(v[j].z * inv), t3 = __float2int_rn(v[j].w * inv);
        int a1, a0, b1, b0, c1, c0, d1, d0;
        dig2(t0, a1, a0); dig2(t1, b1, b0); dig2(t2, c1, c0); dig2(t3, d1, d0);
        o1[tid + 256 * j] = pack4(a1, b1, c1, d1);
        o0[tid + 256 * j] = pack4(a0, b0, c0, d0);
    }
    if (tid == 0) g_sw[layer * DH + n] = s * (1.f / 16256.f);
}

// ---------------------------------------------------------------------------
// X quantize: per row m (512 elems), warp per row. useG: read g_h else X.
// ---------------------------------------------------------------------------
__global__ void quantx_kernel(const float* __restrict__ X, int useG)
{
    const int warp = threadIdx.x >> 5, lane = threadIdx.x & 31;
    const int row = blockIdx.x * 8 + warp;
    const float* src = useG ? (const float*)g_h : X;
    const float* xr = src + (size_t)row * DIN;

    float4 v[4];
    float mx = 0.f;
    #pragma unroll
    for (int j = 0; j < 4; ++j) {
        v[j] = ((const float4*)xr)[lane + 32 * j];
        mx = fmaxf(mx, fmaxf(fmaxf(fabsf(v[j].x), fabsf(v[j].y)),
                             fmaxf(fabsf(v[j].z), fabsf(v[j].w))));
    }
    #pragma unroll
    for (int o = 16; o > 0; o >>= 1) mx = fmaxf(mx, __shfl_xor_sync(~0u, mx, o));
    const float s = fmaxf(mx, 1e-30f);
    const float inv = 16256.f / s;

    uint32_t* o1 = (uint32_t*)(g_xd1 + (size_t)row * DIN);
    uint32_t* o0 = (uint32_t*)(g_xd0 + (size_t)row * DIN);
    #pragma unroll
    for (int j = 0; j < 4; ++j) {
        int t0 = __float2int_rn(v[j].x * inv), t1 = __float2int_rn(v[j].y * inv);
        int t2 = __float2int_rn(v[j].z * inv), t3 = __float2int_rn(v[j].w * inv);
        int a1, a0, b1, b0, c1, c0, d1, d0;
        dig2(t0, a1, a0); dig2(t1, b1, b0); dig2(t2, c1, c0); dig2(t3, d1, d0);
        o1[lane + 32 * j] = pack4(a1, b1, c1, d1);
        o0[lane + 32 * j] = pack4(a0, b0, c0, d0);
    }
    if (lane == 0) g_sx[row] = s * (1.f / 16256.f);
}

// ---------------------------------------------------------------------------
// Layer GEMM: CTA 128x128, 512 threads, 16 warps (4m x 4n, warp tile 32x32),
// BK=64, 4-stage swizzled cp.async pipeline (wait_group 2), int8 m16n8k32.
// MODE selects W slab; MODE<2 writes fp32 g_h, MODE==2 writes Yp.
// ---------------------------------------------------------------------------
template <bool ACT, int MODE>
__global__ __launch_bounds__(512, 1)
void layer_mm(const float* __restrict__ bias, float* __restrict__ Yp)
{
    const int8_t* Wd1 = g_wd1 + (size_t)MODE * DH * KTOT;
    const int8_t* Wd0 = g_wd0 + (size_t)MODE * DH * KTOT;

    extern __shared__ char sm[];
    const uint32_t sb = smem_u32(sm);
    float* wsm = (float*)(sm + WSM_OFF);
    float* bsm = (float*)(sm + BSM_OFF);
    float* sxs = (float*)(sm + SXS_OFF);
    float* sws = (float*)(sm + SWS_OFF);
    float* tot = (float*)(sm + TOT_OFF);

    const int tid  = threadIdx.x;
    const int lane = tid & 31;
    const int warp = tid >> 5;
    const int g = lane >> 2, t = lane & 3;
    const int wm = warp >> 2, wn = warp & 3;        // 4m x 4n warps, tile 32x32
    const int mBase = blockIdx.y * BM;
    const int nBase = blockIdx.x * BN;

    for (int i = tid; i < BM * EXPN; i += 512) wsm[i] = g_w[(size_t)mBase * EXPN + i];
    for (int i = tid; i < EXPN * BN; i += 512) bsm[i] = bias[(i >> 7) * DH + nBase + (i & 127)];
    if (tid < 128) {
        sxs[tid] = g_sx[mBase + tid];
        sws[tid] = g_sw[MODE * DH + nBase + tid];
    }
    #pragma unroll
    for (int e = 0; e < 32; ++e) tot[e * 512 + tid] = 0.f;
    __syncthreads();

    int hi[2][4][4], mid[2][4][4];
    #pragma unroll
    for (int mt = 0; mt < 2; ++mt)
        #pragma unroll
        for (int nf = 0; nf < 4; ++nf)
            #pragma unroll
            for (int q = 0; q < 4; ++q) { hi[mt][nf][q] = 0; mid[mt][nf][q] = 0; }

    // ldmatrix addressing (rows 64B wide; 16B chunk swizzle c ^ ((row>>1)&3))
    const int a_rbase = wm * 32 + (lane & 15);
    const int a_h     = (lane >> 4) & 1;
    const int a_cxor  = ((lane & 15) >> 1) & 3;
    const int b_rbase = wn * 32 + (lane & 7) + ((lane >> 4) << 3);
    const int b_h     = (lane >> 3) & 1;
    const int b_cxor  = ((lane & 7) >> 1) & 3;

    // cp.async: thread j -> row j>>2, chunk j&3
    const int cr = tid >> 2, cc = tid & 3;
    const uint32_t cp_d = (uint32_t)(cr * 64 + ((cc ^ ((cr >> 1) & 3)) << 4));

    auto cpAB = [&](int it, int buf) {
        const uint32_t base = sb + buf * STAGE;
        const int i0 = (it & 7) * BK;
        const size_t sa = (size_t)(mBase + cr) * DIN + i0 + cc * 16;
        cp16(base + cp_d, g_xd1 + sa);
        cp16(base + OFF_AD0 + cp_d, g_xd0 + sa);
        const size_t sbv = (size_t)(nBase + cr) * KTOT + (size_t)it * BK + cc * 16;
        cp16(base + OFF_BE1 + cp_d, Wd1 + sbv);
        cp16(base + OFF_BE0 + cp_d, Wd0 + sbv);
    };

    cpAB(0, 0);
    asm volatile("cp.async.commit_group;" ::: "memory");
    cpAB(1, 1);
    asm volatile("cp.async.commit_group;" ::: "memory");
    cpAB(2, 2);
    asm volatile("cp.async.commit_group;" ::: "memory");

    int buf = 0;
    for (int it = 0; it < NIT; ++it) {
        asm volatile("cp.async.wait_group 2;" ::: "memory");
        __syncthreads();

        if (it + 3 < NIT) cpAB(it + 3, (it + 3) & (NSTAGE - 1));
        asm volatile("cp.async.commit_group;" ::: "memory");   // may be empty

        const uint32_t st = sb + buf * STAGE;
        #pragma unroll
        for (int ks = 0; ks < 2; ++ks) {
            uint32_t a1[2][4], a0[2][4];
            #pragma unroll
            for (int mt = 0; mt < 2; ++mt) {
                const int row = a_rbase + mt * 16;
                const int c = (ks * 2 + a_h) ^ a_cxor;
                const uint32_t ao = st + (uint32_t)(row * 64 + (c << 4));
                ldsm4(a1[mt], ao);
                ldsm4(a0[mt], ao + OFF_AD0);
            }
            #pragma unroll
            for (int nh = 0; nh < 2; ++nh) {
                const int nrow = b_rbase + nh * 16;
                const int c = (ks * 2 + b_h) ^ b_cxor;
                const uint32_t bo = st + OFF_BE1 + (uint32_t)(nrow * 64 + (c << 4));
                uint32_t b1r[4], b0r[4];
                ldsm4(b1r, bo);
                ldsm4(b0r, bo + (OFF_BE0 - OFF_BE1));
                #pragma unroll
                for (int mt = 0; mt < 2; ++mt)
                    #pragma unroll
                    for (int p = 0; p < 2; ++p) {
                        const int nf = nh * 2 + p;
                        mma_s8(hi [mt][nf], a1[mt], &b1r[p * 2]);
                        mma_s8(mid[mt][nf], a1[mt], &b0r[p * 2]);
                        mma_s8(mid[mt][nf], a0[mt], &b1r[p * 2]);
                    }
            }
        }

        if ((it & 7) == 7) {   // expert boundary: fold into fp32 smem total
            const int e = it >> 3;
            #pragma unroll
            for (int mt = 0; mt < 2; ++mt) {
                const int r0 = wm * 32 + mt * 16 + g;
                const float w0 = wsm[r0 * 8 + e];
                const float w1 = wsm[(r0 + 8) * 8 + e];
                #pragma unroll
                for (int nf = 0; nf < 4; ++nf)
                    #pragma unroll
                    for (int q = 0; q < 4; ++q) {
                        float v = fmaf(16384.f, (float)hi[mt][nf][q],
                                       128.f * (float)mid[mt][nf][q]);
                        float* sp = tot + (mt * 16 + nf * 4 + q) * 512 + tid;
                        *sp = fmaf((q & 2) ? w1 : w0, v, *sp);
                        hi[mt][nf][q] = 0; mid[mt][nf][q] = 0;
                    }
            }
        }

        buf = (buf + 1) & (NSTAGE - 1);
    }

    // epilogue: scale by sx*sw, + w @ bias, activation, store fp32
    float* Y = (MODE == 2) ? Yp : (float*)g_h;
    #pragma unroll
    for (int mt = 0; mt < 2; ++mt) {
        const int r0 = wm * 32 + mt * 16 + g;
        const float s0 = sxs[r0], s1 = sxs[r0 + 8];
        float w0[8], w1[8];
        #pragma unroll
        for (int e = 0; e < 8; ++e) {
            w0[e] = wsm[r0 * 8 + e];
            w1[e] = wsm[(r0 + 8) * 8 + e];
        }
        #pragma unroll
        for (int nf = 0; nf < 4; ++nf) {
            const int c = wn * 32 + nf * 8 + t * 2;
            float b00 = 0.f, b01 = 0.f, b10 = 0.f, b11 = 0.f;
            #pragma unroll
            for (int e = 0; e < 8; ++e) {
                float be0 = bsm[e * 128 + c], be1 = bsm[e * 128 + c + 1];
                b00 = fmaf(w0[e], be0, b00); b01 = fmaf(w0[e], be1, b01);
                b10 = fmaf(w1[e], be0, b10); b11 = fmaf(w1[e], be1, b11);
            }
            const int eb = mt * 16 + nf * 4;
            const float sc0 = sws[c], sc1 = sws[c + 1];
            float v0 = tot[(eb + 0) * 512 + tid] * (s0 * sc0) + b00;
            float v1 = tot[(eb + 1) * 512 + tid] * (s0 * sc1) + b01;
            float v2 = tot[(eb + 2) * 512 + tid] * (s1 * sc0) + b10;
            float v3 = tot[(eb + 3) * 512 + tid] * (s1 * sc1) + b11;
            if (ACT) { v0 = eluf(v0); v1 = eluf(v1); v2 = eluf(v2); v3 = eluf(v3); }
            *(float2*)(Y + (size_t)(mBase + r0)     * DH + nBase + c) = make_float2(v0, v1);
            *(float2*)(Y + (size_t)(mBase + r0 + 8) * DH + nBase + c) = make_float2(v2, v3);
        }
    }
}

// ---------------------------------------------------------------------------
extern "C" void kernel_launch(void* const* d_in, const int* in_sizes, int n_in,
                              void* d_out, int out_size)
{
    const float* z   = (const float*)d_in[0];
    const void*  idx = (const void*)d_in[1];
    const float* Wg1 = (const float*)d_in[2];
    const float* bg1 = (const float*)d_in[3];
    const float* Wg2 = (const float*)d_in[4];
    const float* bg2 = (const float*)d_in[5];
    const float* Wg3 = (const float*)d_in[6];
    const float* bg3 = (const float*)d_in[7];
    const float* W1  = (const float*)d_in[8];
    const float* b1  = (const float*)d_in[9];
    const float* W2  = (const float*)d_in[10];
    const float* b2  = (const float*)d_in[11];
    const float* W3  = (const float*)d_in[12];
    const float* b3  = (const float*)d_in[13];
    float* out = (float*)d_out;

    cudaFuncSetAttribute(layer_mm<true , 0>, cudaFuncAttributeMaxDynamicSharedMemorySize, SMEM_BYTES);
    cudaFuncSetAttribute(layer_mm<true , 1>, cudaFuncAttributeMaxDynamicSharedMemorySize, SMEM_BYTES);
    cudaFuncSetAttribute(layer_mm<false, 2>, cudaFuncAttributeMaxDynamicSharedMemorySize, SMEM_BYTES);

    // weight prep: transpose fp32, then per-column 2-digit int8 quantization
    dim3 wgrid(KTOT / 32, DH / 32);   // (128, 16)
    dim3 wblk(32, 8);
    wtrans_kernel<<<wgrid, wblk>>>(W1, 0);
    wtrans_kernel<<<wgrid, wblk>>>(W2, 1);
    wtrans_kernel<<<wgrid, wblk>>>(W3, 2);
    quantw_kernel<<<dim3(DH, 3), 256>>>();

    gating_kernel<<<1024, 256>>>(z, idx, Wg1, bg1, Wg2, bg2, Wg3, bg3);

    dim3 grid(DH / BN, BATCH / BM);   // (4, 512)

    quantx_kernel<<<BATCH / 8, 256>>>(z, 0);
    layer_mm<true , 0><<<grid, 512, SMEM_BYTES>>>(b1, nullptr);
    quantx_kernel<<<BATCH / 8, 256>>>(nullptr, 1);
    layer_mm<true , 1><<<grid, 512, SMEM_BYTES>>>(b2, nullptr);
    quantx_kernel<<<BATCH / 8, 256>>>(nullptr, 1);
    layer_mm<false, 2><<<grid, 512, SMEM_BYTES>>>(b3, out);
}

// round 12
// speedup vs baseline: 2.5494x; 2.5494x over previous
#include <cuda_runtime.h>
#include <cuda_bf16.h>
#include <cstdint>

// ---------------------------------------------------------------------------
// GatedExpertsEncoder (sm_103a, legacy mma.sync path — tcgen05 unavailable via
// this toolchain's compute_103 PTX stage; int8 mma measured 6x de-rated).
// out = sum_e w[:,e] * act(X @ W_e + b_e), 3 layers, E=8 soft MoE.
// bf16 split precision (ah*bh + ah*bl + al*bh), fp32 accumulate m16n8k16.
// X and W pre-split into bf16 hi/lo globals; mainloop = cp.async + ldmatrix +
// MMA. Per-expert register partials folded with w_e at expert boundaries into
// per-thread-private SMEM totals (frees ~32 regs so ptxas can double-buffer
// fragments across the ks steps). 3-stage SW128-swizzled pipeline, wg 1.
// ---------------------------------------------------------------------------

static constexpr int BATCH = 65536;
static constexpr int DIN   = 512;
static constexpr int DH    = 512;
static constexpr int EXPN  = 8;
static constexpr int KTOT  = EXPN * DIN;   // 4096

static constexpr int BM = 128, BN = 128, BK = 64;
static constexpr int NIT = KTOT / BK;      // 64
static constexpr int NSTAGE = 3;

// swizzled tiles: 128 rows x 128B (64 bf16), chunk16 swizzle c^(r&7)
static constexpr int TILEB  = 128 * 128;            // 16384 B
static constexpr int OFF_AL = TILEB;                // 16384
static constexpr int OFF_BH = 2 * TILEB;            // 32768
static constexpr int STAGE  = 4 * TILEB;            // 65536 B (Ah,Al,Bh,Bl)
static constexpr int WSM_OFF = NSTAGE * STAGE;      // 196608... (see below)
// NOTE: with NSTAGE=3, stages end at 196608; but we need room for tot (64KB).
// Recompute: 3*65536 = 196608; +wsm 4096 +bsm 4096 + tot 65536 = 270336 > cap.
// => shrink stage to 3 tiles is impossible (4 operand tiles). Instead BK=64
// tiles stay, but we drop to NSTAGE=3 NOT possible with tot... so use
// NSTAGE=2? Too shallow. Resolution: stage holds Ah,Al,Bh,Bl = 64KB is wrong:
// A tile = 128 rows x 128B = 16KB; stage = 4 tiles = 64KB?? R8 used 48KB
// because STAGE = 3*TILEB (A hi, A lo, B hi, B lo => 4 tiles = 4*16KB=64KB?
// R8 had OFF_AL=TILEB, OFF_BH=2*TILEB and B LO at OFF_BH+TILEB inside same
// stage => STAGE was 4*TILEB=65536? No: R8 STAGE=3*TILEB=49152 with B lo
// accessed at bo+TILEB... that aliased the NEXT stage! Actually R8's bf16
// 3-product needs Bl as well (product ah*bl) => R8 stored Bl at OFF_BH+TILEB
// = 3*TILEB which is stage+0 of next stage?? R8 defined STAGE=4*TILEB=65536B.
// (R8 source: OFF_BL = 3*TILEB; STAGE = 4*TILEB.) Correct. So stage=64KB.
// Budget: NSTAGE*65536 + 4096 + 4096 + 65536 tot <= 232448
//   -> NSTAGE = 1 impossible. So tot-in-smem requires BK=32 stages (32KB):
//   NSTAGE=4 -> 131072 + 8192 + 65536 = 204800 OK.
static constexpr int BK2     = 32;                  // actual K per stage
static constexpr int NIT2    = KTOT / BK2;          // 128
static constexpr int TILE2   = 128 * 64;            // 8192 B (128 rows x 64B)
static constexpr int S_AL    = TILE2;               // 8192
static constexpr int S_BH    = 2 * TILE2;           // 16384
static constexpr int S_BL    = 3 * TILE2;           // 24576
static constexpr int STAGE2  = 4 * TILE2;           // 32768
static constexpr int NSTG2   = 4;
static constexpr int WSM2    = NSTG2 * STAGE2;      // 131072 (128*8 fp32)
static constexpr int BSM2    = WSM2 + 4096;         // 135168 (8*128 fp32)
static constexpr int TOT2    = BSM2 + 4096;         // 139264 (32*512 fp32)
static constexpr int SMEM_BYTES = TOT2 + 65536;     // 204800

// ------------------------------ scratch -----------------------------------
__device__ __align__(16) float g_w [(size_t)BATCH * EXPN];
__device__ __align__(16) __nv_bfloat16 g_xah[(size_t)BATCH * DIN];
__device__ __align__(16) __nv_bfloat16 g_xal[(size_t)BATCH * DIN];
__device__ __align__(16) __nv_bfloat16 g_xbh[(size_t)BATCH * DIN];
__device__ __align__(16) __nv_bfloat16 g_xbl[(size_t)BATCH * DIN];
__device__ __align__(16) __nv_bfloat16 g_wth[(size_t)3 * DH * KTOT];
__device__ __align__(16) __nv_bfloat16 g_wtl[(size_t)3 * DH * KTOT];

// ------------------------------ helpers -----------------------------------
__device__ __forceinline__ float eluf(float x) { return x > 0.f ? x : expm1f(x); }

__device__ __forceinline__ uint32_t packbf2(float vlo, float vhi) {
    uint32_t r;
    asm("cvt.rn.bf16x2.f32 %0, %1, %2;" : "=r"(r) : "f"(vhi), "f"(vlo));
    return r;
}
__device__ __forceinline__ void splitbf2(float v0, float v1, uint32_t& hi, uint32_t& lo) {
    hi = packbf2(v0, v1);
    float h0 = __uint_as_float(hi << 16);
    float h1 = __uint_as_float(hi & 0xFFFF0000u);
    lo = packbf2(v0 - h0, v1 - h1);
}
__device__ __forceinline__ uint32_t smem_u32(const void* p) {
    uint32_t a;
    asm("{ .reg .u64 t; cvta.to.shared.u64 t, %1; cvt.u32.u64 %0, t; }" : "=r"(a) : "l"(p));
    return a;
}
__device__ __forceinline__ void cp16(uint32_t dst, const void* src) {
    asm volatile("cp.async.cg.shared.global [%0], [%1], 16;" :: "r"(dst), "l"(src) : "memory");
}
__device__ __forceinline__ void ldsm4(uint32_t r[4], uint32_t addr) {
    asm volatile("ldmatrix.sync.aligned.m8n8.x4.shared.b16 {%0,%1,%2,%3}, [%4];"
                 : "=r"(r[0]), "=r"(r[1]), "=r"(r[2]), "=r"(r[3]) : "r"(addr));
}
__device__ __forceinline__ void mma_bf16(float c[4], const uint32_t a[4], const uint32_t b[2]) {
    asm("mma.sync.aligned.m16n8k16.row.col.f32.bf16.bf16.f32 "
        "{%0,%1,%2,%3}, {%4,%5,%6,%7}, {%8,%9}, {%0,%1,%2,%3};\n"
        : "+f"(c[0]), "+f"(c[1]), "+f"(c[2]), "+f"(c[3])
        : "r"(a[0]), "r"(a[1]), "r"(a[2]), "r"(a[3]), "r"(b[0]), "r"(b[1]));
}

// ---------------------------------------------------------------------------
// Gating MLP (proven since R3).
// ---------------------------------------------------------------------------
__global__ void gating_kernel(const float* __restrict__ z,
                              const void* __restrict__ idx_raw,
                              const float* __restrict__ Wg1, const float* __restrict__ bg1,
                              const float* __restrict__ Wg2, const float* __restrict__ bg2,
                              const float* __restrict__ Wg3, const float* __restrict__ bg3)
{
    __shared__ float bufA[8][128];
    __shared__ float bufB[8][128];
    const int warp = threadIdx.x >> 5;
    const int lane = threadIdx.x & 31;
    const int gwarp = blockIdx.x * 8 + warp;
    const int nwarp = gridDim.x * 8;

    const int* idx32 = (const int*)idx_raw;
    const bool is64 = (idx32[1] == 0);

    for (int row = gwarp; row < BATCH; row += nwarp) {
        const float* zr = z + (size_t)row * DIN;
        for (int k = lane; k < 128; k += 32) {
            int col = is64 ? idx32[2 * k] : idx32[k];
            bufA[warp][k] = zr[col & (DIN - 1)];
        }
        __syncwarp();
        {
            float s0 = bg1[lane * 4 + 0], s1 = bg1[lane * 4 + 1];
            float s2 = bg1[lane * 4 + 2], s3 = bg1[lane * 4 + 3];
            #pragma unroll 8
            for (int k = 0; k < 128; ++k) {
                float xk = bufA[warp][k];
                float4 wv = *(const float4*)(Wg1 + k * 128 + lane * 4);
                s0 = fmaf(xk, wv.x, s0); s1 = fmaf(xk, wv.y, s1);
                s2 = fmaf(xk, wv.z, s2); s3 = fmaf(xk, wv.w, s3);
            }
            bufB[warp][lane * 4 + 0] = eluf(s0);
            bufB[warp][lane * 4 + 1] = eluf(s1);
            bufB[warp][lane * 4 + 2] = eluf(s2);
            bufB[warp][lane * 4 + 3] = eluf(s3);
        }
        __syncwarp();
        {
            float s0 = bg2[lane * 4 + 0], s1 = bg2[lane * 4 + 1];
            float s2 = bg2[lane * 4 + 2], s3 = bg2[lane * 4 + 3];
            #pragma unroll 8
            for (int k = 0; k < 128; ++k) {
                float xk = bufB[warp][k];
                float4 wv = *(const float4*)(Wg2 + k * 128 + lane * 4);
                s0 = fmaf(xk, wv.x, s0); s1 = fmaf(xk, wv.y, s1);
                s2 = fmaf(xk, wv.z, s2); s3 = fmaf(xk, wv.w, s3);
            }
            bufA[warp][lane * 4 + 0] = eluf(s0);
            bufA[warp][lane * 4 + 1] = eluf(s1);
            bufA[warp][lane * 4 + 2] = eluf(s2);
            bufA[warp][lane * 4 + 3] = eluf(s3);
        }
        __syncwarp();
        if (lane < 8) {
            float s = bg3[lane];
            #pragma unroll 8
            for (int k = 0; k < 128; ++k)
                s = fmaf(bufA[warp][k], Wg3[k * 8 + lane], s);
            g_w[(size_t)row * 8 + lane] = s;
        }
        __syncwarp();
    }
}

// ---------------------------------------------------------------------------
// W pre-transpose+split: W[k=4096][o=512] fp32 -> Wt hi/lo [o=512][k=4096] bf16
// ---------------------------------------------------------------------------
__global__ void wsplit_kernel(const float* __restrict__ W, int layer)
{
    __shared__ float T[32][33];
    __nv_bfloat16* oh = g_wth + (size_t)layer * DH * KTOT;
    __nv_bfloat16* ol = g_wtl + (size_t)layer * DH * KTOT;
    const int kt = blockIdx.x * 32, ot = blockIdx.y * 32;
    const int tx = threadIdx.x, ty = threadIdx.y;   // 32 x 8
    #pragma unroll
    for (int i = 0; i < 4; ++i)
        T[ty + 8 * i][tx] = W[(size_t)(kt + ty + 8 * i) * DH + ot + tx];
    __syncthreads();
    #pragma unroll
    for (int i = 0; i < 4; ++i) {
        const int o = ot + ty + 8 * i, k = kt + tx;
        float v = T[tx][ty + 8 * i];
        __nv_bfloat16 h = __float2bfloat16(v);
        oh[(size_t)o * KTOT + k] = h;
        ol[(size_t)o * KTOT + k] = __float2bfloat16(v - __bfloat162float(h));
    }
}

// ---------------------------------------------------------------------------
// z -> split bf16 hi/lo (layer-1 input)
// ---------------------------------------------------------------------------
__global__ void splitz_kernel(const float* __restrict__ z)
{
    const size_t i = (size_t)(blockIdx.x * blockDim.x + threadIdx.x);
    const size_t n4 = (size_t)BATCH * DIN / 4;
    if (i >= n4) return;
    float4 v = ((const float4*)z)[i];
    uint32_t h0, l0, h1, l1;
    splitbf2(v.x, v.y, h0, l0);
    splitbf2(v.z, v.w, h1, l1);
    ((uint2*)g_xah)[i] = make_uint2(h0, h1);
    ((uint2*)g_xal)[i] = make_uint2(l0, l1);
}

// ---------------------------------------------------------------------------
// Layer kernel: CTA 128x128, 512 threads, 16 warps (4m x 4n, warp tile 32x32),
// BK=32, 4-stage swizzled cp.async pipeline (wait_group 2). part in regs,
// running totals in per-thread-private SMEM (32 fp32/thread).
// MODE 0: Xa -> Xb split; MODE 1: Xb -> Xa split; MODE 2: Xa -> fp32 out.
// ---------------------------------------------------------------------------
template <bool ACT, int MODE>
__global__ __launch_bounds__(512, 1)
void layer_mm(const float* __restrict__ bias, float* __restrict__ Yp)
{
    const __nv_bfloat16* Xh = (MODE == 1) ? g_xbh : g_xah;
    const __nv_bfloat16* Xl = (MODE == 1) ? g_xbl : g_xal;
    const __nv_bfloat16* Wth = g_wth + (size_t)MODE * DH * KTOT;
    const __nv_bfloat16* Wtl = g_wtl + (size_t)MODE * DH * KTOT;

    extern __shared__ char sm[];
    const uint32_t sb = smem_u32(sm);
    float* wsm = (float*)(sm + WSM2);
    float* bsm = (float*)(sm + BSM2);
    float* tot = (float*)(sm + TOT2);

    const int tid  = threadIdx.x;
    const int lane = tid & 31;
    const int warp = tid >> 5;
    const int g = lane >> 2, t = lane & 3;
    const int wm = warp >> 2, wn = warp & 3;        // 4m x 4n warps, tile 32x32
    const int mBase = blockIdx.y * BM;
    const int nBase = blockIdx.x * BN;

    for (int i = tid; i < BM * EXPN; i += 512) wsm[i] = g_w[(size_t)mBase * EXPN + i];
    for (int i = tid; i < EXPN * BN; i += 512) bsm[i] = bias[(i >> 7) * DH + nBase + (i & 127)];
    #pragma unroll
    for (int j = 0; j < 32; ++j) tot[j * 512 + tid] = 0.f;

    float part[2][4][4];
    #pragma unroll
    for (int mt = 0; mt < 2; ++mt)
        #pragma unroll
        for (int nf = 0; nf < 4; ++nf)
            #pragma unroll
            for (int q = 0; q < 4; ++q) part[mt][nf][q] = 0.f;

    // ldmatrix addressing: rows 64B wide, 16B chunk swizzle c ^ ((row>>1)&3)
    const int a_row = wm * 32 + (lane & 15);        // + mt*16
    const int a_h   = (lane >> 4) & 1;              // chunk base (+ ks*2)
    const int b_row = wn * 32 + (lane & 7) + ((lane & 16) >> 1);   // + p*16
    const int b_h   = (lane >> 3) & 1;

    // cp.async: thread j -> row j>>2 (0..127), chunk j&3
    const int cr = tid >> 2, cc = tid & 3;
    const uint32_t cp_d = (uint32_t)(cr * 64 + ((cc ^ ((cr >> 1) & 3)) << 4));

    auto cpAB = [&](int it, int buf) {
        const uint32_t base = sb + buf * STAGE2;
        const int i0 = (it & 15) * BK2;
        {   // A hi/lo
            const size_t s = (size_t)(mBase + cr) * DIN + i0 + cc * 8;
            cp16(base + cp_d, Xh + s);
            cp16(base + S_AL + cp_d, Xl + s);
        }
        {   // B hi/lo
            const size_t s = (size_t)(nBase + cr) * KTOT + (size_t)it * BK2 + cc * 8;
            cp16(base + S_BH + cp_d, Wth + s);
            cp16(base + S_BL + cp_d, Wtl + s);
        }
    };

    // prologue: fill stages 0,1,2
    cpAB(0, 0);
    asm volatile("cp.async.commit_group;" ::: "memory");
    cpAB(1, 1);
    asm volatile("cp.async.commit_group;" ::: "memory");
    cpAB(2, 2);
    asm volatile("cp.async.commit_group;" ::: "memory");

    int buf = 0;
    for (int it = 0; it < NIT2; ++it) {
        asm volatile("cp.async.wait_group 2;" ::: "memory");
        __syncthreads();

        if (it + 3 < NIT2) cpAB(it + 3, (it + 3) & (NSTG2 - 1));
        asm volatile("cp.async.commit_group;" ::: "memory");   // may be empty

        const uint32_t st = sb + buf * STAGE2;
        #pragma unroll
        for (int ks = 0; ks < 2; ++ks) {
            uint32_t ah[2][4], al[2][4], bh[2][4], bl[2][4];
            #pragma unroll
            for (int mt = 0; mt < 2; ++mt) {
                const int r = a_row + mt * 16;
                const int c = (ks * 2 + a_h) ^ ((r >> 1) & 3);
                uint32_t ao = st + (uint32_t)(r * 64 + (c << 4));
                ldsm4(ah[mt], ao);
                ldsm4(al[mt], ao + S_AL);
            }
            #pragma unroll
            for (int p = 0; p < 2; ++p) {
                const int r = b_row + p * 16;
                const int c = (ks * 2 + b_h) ^ ((r >> 1) & 3);
                uint32_t bo = st + S_BH + (uint32_t)(r * 64 + (c << 4));
                ldsm4(bh[p], bo);
                ldsm4(bl[p], bo + (S_BL - S_BH));
            }
            #pragma unroll
            for (int mt = 0; mt < 2; ++mt)
                #pragma unroll
                for (int nf = 0; nf < 4; ++nf)
                    mma_bf16(part[mt][nf], ah[mt], &bh[nf >> 1][(nf & 1) * 2]);
            #pragma unroll
            for (int mt = 0; mt < 2; ++mt)
                #pragma unroll
                for (int nf = 0; nf < 4; ++nf)
                    mma_bf16(part[mt][nf], ah[mt], &bl[nf >> 1][(nf & 1) * 2]);
            #pragma unroll
            for (int mt = 0; mt < 2; ++mt)
                #pragma unroll
                for (int nf = 0; nf < 4; ++nf)
                    mma_bf16(part[mt][nf], al[mt], &bh[nf >> 1][(nf & 1) * 2]);
        }

        if ((it & 15) == 15) {   // expert boundary: fold into SMEM totals
            const int e = it >> 4;
            #pragma unroll
            for (int mt = 0; mt < 2; ++mt) {
                const int r0 = wm * 32 + mt * 16 + g;
                const float w0 = wsm[r0 * 8 + e];
                const float w1 = wsm[(r0 + 8) * 8 + e];
                #pragma unroll
                for (int nf = 0; nf < 4; ++nf)
                    #pragma unroll
                    for (int q = 0; q < 4; ++q) {
                        float* sp = tot + (mt * 16 + nf * 4 + q) * 512 + tid;
                        *sp = fmaf((q & 2) ? w1 : w0, part[mt][nf][q], *sp);
                        part[mt][nf][q] = 0.f;
                    }
            }
        }

        buf = (buf + 1) & (NSTG2 - 1);
    }

    // epilogue: + w @ bias, activation, store (split bf16 for MODE<2)
    #pragma unroll
    for (int mt = 0; mt < 2; ++mt) {
        const int r0 = wm * 32 + mt * 16 + g;
        float w0[8], w1[8];
        #pragma unroll
        for (int e = 0; e < 8; ++e) {
            w0[e] = wsm[r0 * 8 + e];
            w1[e] = wsm[(r0 + 8) * 8 + e];
        }
        #pragma unroll
        for (int nf = 0; nf < 4; ++nf) {
            const int c = wn * 32 + nf * 8 + t * 2;
            float b00 = 0.f, b01 = 0.f, b10 = 0.f, b11 = 0.f;
            #pragma unroll
            for (int e = 0; e < 8; ++e) {
                float be0 = bsm[e * 128 + c], be1 = bsm[e * 128 + c + 1];
                b00 = fmaf(w0[e], be0, b00); b01 = fmaf(w0[e], be1, b01);
                b10 = fmaf(w1[e], be0, b10); b11 = fmaf(w1[e], be1, b11);
            }
            const int eb = mt * 16 + nf * 4;
            float v0 = tot[(eb + 0) * 512 + tid] + b00;
            float v1 = tot[(eb + 1) * 512 + tid] + b01;
            float v2 = tot[(eb + 2) * 512 + tid] + b10;
            float v3 = tot[(eb + 3) * 512 + tid] + b11;
            if (ACT) { v0 = eluf(v0); v1 = eluf(v1); v2 = eluf(v2); v3 = eluf(v3); }
            const size_t o0 = (size_t)(mBase + r0) * DH + nBase + c;
            const size_t o1 = (size_t)(mBase + r0 + 8) * DH + nBase + c;
            if (MODE == 2) {
                *(float2*)(Yp + o0) = make_float2(v0, v1);
                *(float2*)(Yp + o1) = make_float2(v2, v3);
            } else {
                __nv_bfloat16* oh = (MODE == 0) ? g_xbh : g_xah;
                __nv_bfloat16* ol = (MODE == 0) ? g_xbl : g_xal;
                uint32_t h0, l0, h1, l1;
                splitbf2(v0, v1, h0, l0);
                splitbf2(v2, v3, h1, l1);
                *(uint32_t*)(oh + o0) = h0;
                *(uint32_t*)(ol + o0) = l0;
                *(uint32_t*)(oh + o1) = h1;
                *(uint32_t*)(ol + o1) = l1;
            }
        }
    }
}

// ---------------------------------------------------------------------------
extern "C" void kernel_launch(void* const* d_in, const int* in_sizes, int n_in,
                              void* d_out, int out_size)
{
    const float* z   = (const float*)d_in[0];
    const void*  idx = (const void*)d_in[1];
    const float* Wg1 = (const float*)d_in[2];
    const float* bg1 = (const float*)d_in[3];
    const float* Wg2 = (const float*)d_in[4];
    const float* bg2 = (const float*)d_in[5];
    const float* Wg3 = (const float*)d_in[6];
    const float* bg3 = (const float*)d_in[7];
    const float* W1  = (const float*)d_in[8];
    const float* b1  = (const float*)d_in[9];
    const float* W2  = (const float*)d_in[10];
    const float* b2  = (const float*)d_in[11];
    const float* W3  = (const float*)d_in[12];
    const float* b3  = (const float*)d_in[13];
    float* out = (float*)d_out;

    cudaFuncSetAttribute(layer_mm<true , 0>, cudaFuncAttributeMaxDynamicSharedMemorySize, SMEM_BYTES);
    cudaFuncSetAttribute(layer_mm<true , 1>, cudaFuncAttributeMaxDynamicSharedMemorySize, SMEM_BYTES);
    cudaFuncSetAttribute(layer_mm<false, 2>, cudaFuncAttributeMaxDynamicSharedMemorySize, SMEM_BYTES);

    splitz_kernel<<<(BATCH * DIN / 4 + 255) / 256, 256>>>(z);

    dim3 wgrid(KTOT / 32, DH / 32);   // (128, 16)
    dim3 wblk(32, 8);
    wsplit_kernel<<<wgrid, wblk>>>(W1, 0);
    wsplit_kernel<<<wgrid, wblk>>>(W2, 1);
    wsplit_kernel<<<wgrid, wblk>>>(W3, 2);

    gating_kernel<<<1024, 256>>>(z, idx, Wg1, bg1, Wg2, bg2, Wg3, bg3);

    dim3 grid(DH / BN, BATCH / BM);   // (4, 512)
    layer_mm<true , 0><<<grid, 512, SMEM_BYTES>>>(b1, nullptr);
    layer_mm<true , 1><<<grid, 512, SMEM_BYTES>>>(b2, nullptr);
    layer_mm<false, 2><<<grid, 512, SMEM_BYTES>>>(b3, out);
}

// round 13
// speedup vs baseline: 2.8953x; 1.1357x over previous
#include <cuda_runtime.h>
#include <cuda_bf16.h>
#include <cstdint>

// ---------------------------------------------------------------------------
// GatedExpertsEncoder (sm_103a, legacy mma.sync path — tcgen05 unavailable via
// this toolchain's compute_103 PTX stage; int8 mma measured ~6x de-rated).
// out = sum_e w[:,e] * act(X @ W_e + b_e), 3 layers, E=8 soft MoE.
// bf16 split precision (ah*bh + ah*bl + al*bh), fp32 accumulate m16n8k16.
// X and W pre-split into bf16 hi/lo globals; mainloop = cp.async + ldmatrix +
// MMA. Per-expert register partials folded with w_e at expert boundaries.
// R13 = R8 with warp tile 64x32 at 256 threads (8 warps, 2m x 4n): MMA:LDSM
// ratio 4:1 (vs 3:1), crossbar traffic -25%, regs ~190 (cap 255 at 256 thr).
// ---------------------------------------------------------------------------

static constexpr int BATCH = 65536;
static constexpr int DIN   = 512;
static constexpr int DH    = 512;
static constexpr int EXPN  = 8;
static constexpr int KTOT  = EXPN * DIN;   // 4096

static constexpr int BM = 128, BN = 128, BK = 64;
static constexpr int NIT = KTOT / BK;      // 64
static constexpr int NSTAGE = 3;
static constexpr int NTHR = 256;

// swizzled tiles: 128 rows x 128B (64 bf16), chunk16 swizzle c^(r&7)
static constexpr int TILEB  = 128 * 128;            // 16384 B
static constexpr int OFF_AL = TILEB;                // 16384
static constexpr int OFF_BH = 2 * TILEB;            // 32768
static constexpr int OFF_BL = 3 * TILEB;            // 49152
static constexpr int STAGE  = 4 * TILEB;            // 65536 B
static constexpr int WSM_OFF = NSTAGE * STAGE;      // 196608 (128*8 fp32)
static constexpr int BSM_OFF = WSM_OFF + 4096;      // 200704 (8*128 fp32)
static constexpr int SMEM_BYTES = BSM_OFF + 4096;   // 204800

// ------------------------------ scratch -----------------------------------
__device__ __align__(16) float g_w [(size_t)BATCH * EXPN];
__device__ __align__(16) __nv_bfloat16 g_xah[(size_t)BATCH * DIN];
__device__ __align__(16) __nv_bfloat16 g_xal[(size_t)BATCH * DIN];
__device__ __align__(16) __nv_bfloat16 g_xbh[(size_t)BATCH * DIN];
__device__ __align__(16) __nv_bfloat16 g_xbl[(size_t)BATCH * DIN];
__device__ __align__(16) __nv_bfloat16 g_wth[(size_t)3 * DH * KTOT];
__device__ __align__(16) __nv_bfloat16 g_wtl[(size_t)3 * DH * KTOT];

// ------------------------------ helpers -----------------------------------
__device__ __forceinline__ float eluf(float x) { return x > 0.f ? x : expm1f(x); }

__device__ __forceinline__ uint32_t packbf2(float vlo, float vhi) {
    uint32_t r;
    asm("cvt.rn.bf16x2.f32 %0, %1, %2;" : "=r"(r) : "f"(vhi), "f"(vlo));
    return r;
}
__device__ __forceinline__ void splitbf2(float v0, float v1, uint32_t& hi, uint32_t& lo) {
    hi = packbf2(v0, v1);
    float h0 = __uint_as_float(hi << 16);
    float h1 = __uint_as_float(hi & 0xFFFF0000u);
    lo = packbf2(v0 - h0, v1 - h1);
}
__device__ __forceinline__ uint32_t smem_u32(const void* p) {
    uint32_t a;
    asm("{ .reg .u64 t; cvta.to.shared.u64 t, %1; cvt.u32.u64 %0, t; }" : "=r"(a) : "l"(p));
    return a;
}
__device__ __forceinline__ void cp16(uint32_t dst, const void* src) {
    asm volatile("cp.async.cg.shared.global [%0], [%1], 16;" :: "r"(dst), "l"(src) : "memory");
}
__device__ __forceinline__ void ldsm4(uint32_t r[4], uint32_t addr) {
    asm volatile("ldmatrix.sync.aligned.m8n8.x4.shared.b16 {%0,%1,%2,%3}, [%4];"
                 : "=r"(r[0]), "=r"(r[1]), "=r"(r[2]), "=r"(r[3]) : "r"(addr));
}
__device__ __forceinline__ void mma_bf16(float c[4], const uint32_t a[4], const uint32_t b[2]) {
    asm("mma.sync.aligned.m16n8k16.row.col.f32.bf16.bf16.f32 "
        "{%0,%1,%2,%3}, {%4,%5,%6,%7}, {%8,%9}, {%0,%1,%2,%3};\n"
        : "+f"(c[0]), "+f"(c[1]), "+f"(c[2]), "+f"(c[3])
        : "r"(a[0]), "r"(a[1]), "r"(a[2]), "r"(a[3]), "r"(b[0]), "r"(b[1]));
}

// ---------------------------------------------------------------------------
// Gating MLP (proven since R3).
// ---------------------------------------------------------------------------
__global__ void gating_kernel(const float* __restrict__ z,
                              const void* __restrict__ idx_raw,
                              const float* __restrict__ Wg1, const float* __restrict__ bg1,
                              const float* __restrict__ Wg2, const float* __restrict__ bg2,
                              const float* __restrict__ Wg3, const float* __restrict__ bg3)
{
    __shared__ float bufA[8][128];
    __shared__ float bufB[8][128];
    const int warp = threadIdx.x >> 5;
    const int lane = threadIdx.x & 31;
    const int gwarp = blockIdx.x * 8 + warp;
    const int nwarp = gridDim.x * 8;

    const int* idx32 = (const int*)idx_raw;
    const bool is64 = (idx32[1] == 0);

    for (int row = gwarp; row < BATCH; row += nwarp) {
        const float* zr = z + (size_t)row * DIN;
        for (int k = lane; k < 128; k += 32) {
            int col = is64 ? idx32[2 * k] : idx32[k];
            bufA[warp][k] = zr[col & (DIN - 1)];
        }
        __syncwarp();
        {
            float s0 = bg1[lane * 4 + 0], s1 = bg1[lane * 4 + 1];
            float s2 = bg1[lane * 4 + 2], s3 = bg1[lane * 4 + 3];
            #pragma unroll 8
            for (int k = 0; k < 128; ++k) {
                float xk = bufA[warp][k];
                float4 wv = *(const float4*)(Wg1 + k * 128 + lane * 4);
                s0 = fmaf(xk, wv.x, s0); s1 = fmaf(xk, wv.y, s1);
                s2 = fmaf(xk, wv.z, s2); s3 = fmaf(xk, wv.w, s3);
            }
            bufB[warp][lane * 4 + 0] = eluf(s0);
            bufB[warp][lane * 4 + 1] = eluf(s1);
            bufB[warp][lane * 4 + 2] = eluf(s2);
            bufB[warp][lane * 4 + 3] = eluf(s3);
        }
        __syncwarp();
        {
            float s0 = bg2[lane * 4 + 0], s1 = bg2[lane * 4 + 1];
            float s2 = bg2[lane * 4 + 2], s3 = bg2[lane * 4 + 3];
            #pragma unroll 8
            for (int k = 0; k < 128; ++k) {
                float xk = bufB[warp][k];
                float4 wv = *(const float4*)(Wg2 + k * 128 + lane * 4);
                s0 = fmaf(xk, wv.x, s0); s1 = fmaf(xk, wv.y, s1);
                s2 = fmaf(xk, wv.z, s2); s3 = fmaf(xk, wv.w, s3);
            }
            bufA[warp][lane * 4 + 0] = eluf(s0);
            bufA[warp][lane * 4 + 1] = eluf(s1);
            bufA[warp][lane * 4 + 2] = eluf(s2);
            bufA[warp][lane * 4 + 3] = eluf(s3);
        }
        __syncwarp();
        if (lane < 8) {
            float s = bg3[lane];
            #pragma unroll 8
            for (int k = 0; k < 128; ++k)
                s = fmaf(bufA[warp][k], Wg3[k * 8 + lane], s);
            g_w[(size_t)row * 8 + lane] = s;
        }
        __syncwarp();
    }
}

// ---------------------------------------------------------------------------
// W pre-transpose+split: W[k=4096][o=512] fp32 -> Wt hi/lo [o=512][k=4096] bf16
// ---------------------------------------------------------------------------
__global__ void wsplit_kernel(const float* __restrict__ W, int layer)
{
    __shared__ float T[32][33];
    __nv_bfloat16* oh = g_wth + (size_t)layer * DH * KTOT;
    __nv_bfloat16* ol = g_wtl + (size_t)layer * DH * KTOT;
    const int kt = blockIdx.x * 32, ot = blockIdx.y * 32;
    const int tx = threadIdx.x, ty = threadIdx.y;   // 32 x 8
    #pragma unroll
    for (int i = 0; i < 4; ++i)
        T[ty + 8 * i][tx] = W[(size_t)(kt + ty + 8 * i) * DH + ot + tx];
    __syncthreads();
    #pragma unroll
    for (int i = 0; i < 4; ++i) {
        const int o = ot + ty + 8 * i, k = kt + tx;
        float v = T[tx][ty + 8 * i];
        __nv_bfloat16 h = __float2bfloat16(v);
        oh[(size_t)o * KTOT + k] = h;
        ol[(size_t)o * KTOT + k] = __float2bfloat16(v - __bfloat162float(h));
    }
}

// ---------------------------------------------------------------------------
// z -> split bf16 hi/lo (layer-1 input)
// ---------------------------------------------------------------------------
__global__ void splitz_kernel(const float* __restrict__ z)
{
    const size_t i = (size_t)(blockIdx.x * blockDim.x + threadIdx.x);
    const size_t n4 = (size_t)BATCH * DIN / 4;
    if (i >= n4) return;
    float4 v = ((const float4*)z)[i];
    uint32_t h0, l0, h1, l1;
    splitbf2(v.x, v.y, h0, l0);
    splitbf2(v.z, v.w, h1, l1);
    ((uint2*)g_xah)[i] = make_uint2(h0, h1);
    ((uint2*)g_xal)[i] = make_uint2(l0, l1);
}

// ---------------------------------------------------------------------------
// Layer kernel: CTA 128x128, 256 threads, 8 warps (2m x 4n, warp tile 64x32),
// BK=64, 3-stage swizzled cp.async pipeline (wait_group 1).
// MODE 0: Xa -> Xb split; MODE 1: Xb -> Xa split; MODE 2: Xa -> fp32 out.
// ---------------------------------------------------------------------------
template <bool ACT, int MODE>
__global__ __launch_bounds__(NTHR, 1)
void layer_mm(const float* __restrict__ bias, float* __restrict__ Yp)
{
    const __nv_bfloat16* Xh = (MODE == 1) ? g_xbh : g_xah;
    const __nv_bfloat16* Xl = (MODE == 1) ? g_xbl : g_xal;
    const __nv_bfloat16* Wth = g_wth + (size_t)MODE * DH * KTOT;
    const __nv_bfloat16* Wtl = g_wtl + (size_t)MODE * DH * KTOT;

    extern __shared__ char sm[];
    const uint32_t sb = smem_u32(sm);
    float* wsm = (float*)(sm + WSM_OFF);
    float* bsm = (float*)(sm + BSM_OFF);

    const int tid  = threadIdx.x;
    const int lane = tid & 31;
    const int warp = tid >> 5;
    const int g = lane >> 2, t = lane & 3;
    const int wm = warp >> 2, wn = warp & 3;        // 2m x 4n warps, tile 64x32
    const int mBase = blockIdx.y * BM;
    const int nBase = blockIdx.x * BN;

    for (int i = tid; i < BM * EXPN; i += NTHR) wsm[i] = g_w[(size_t)mBase * EXPN + i];
    for (int i = tid; i < EXPN * BN; i += NTHR) bsm[i] = bias[(i >> 7) * DH + nBase + (i & 127)];

    float part[4][4][4], tot[4][4][4];
    #pragma unroll
    for (int mt = 0; mt < 4; ++mt)
        #pragma unroll
        for (int nf = 0; nf < 4; ++nf)
            #pragma unroll
            for (int q = 0; q < 4; ++q) { part[mt][nf][q] = 0.f; tot[mt][nf][q] = 0.f; }

    // ldmatrix addressing: addr = tile + row*128 + ((chunk ^ (row&7)) << 4)
    const int a_row0 = wm * 64 + (lane & 15);               // + mt*16 (mult of 8)
    const int a_ch0  = (lane >> 4) & 1;                      // + ks*2
    const int a_xor  = a_row0 & 7;
    const int b_row0 = wn * 32 + (lane & 7) + ((lane & 16) >> 1);  // + p*16
    const int b_ch0  = (lane >> 3) & 1;
    const int b_xor  = b_row0 & 7;

    // cp.async indices: j = tid + 256*u -> row j>>3, chunk j&7
    auto cpAB = [&](int it, int buf) {
        const uint32_t base = sb + buf * STAGE;
        const int i0 = (it & 7) * BK;
        const size_t ko = (size_t)it * BK;
        #pragma unroll
        for (int u = 0; u < 4; ++u) {
            const int j = tid + NTHR * u;
            const int r = j >> 3, c = j & 7;
            const uint32_t d = (uint32_t)(r * 128 + ((c ^ (r & 7)) << 4));
            const size_t sa = (size_t)(mBase + r) * DIN + i0 + c * 8;
            cp16(base + d, Xh + sa);
            cp16(base + OFF_AL + d, Xl + sa);
            const size_t sbv = (size_t)(nBase + r) * KTOT + ko + c * 8;
            cp16(base + OFF_BH + d, Wth + sbv);
            cp16(base + OFF_BL + d, Wtl + sbv);
        }
    };

    // prologue: fill stages 0,1
    cpAB(0, 0);
    asm volatile("cp.async.commit_group;" ::: "memory");
    cpAB(1, 1);
    asm volatile("cp.async.commit_group;" ::: "memory");

    int buf = 0;
    for (int it = 0; it < NIT; ++it) {
        asm volatile("cp.async.wait_group 1;" ::: "memory");
        __syncthreads();

        if (it + 2 < NIT) cpAB(it + 2, (it + 2) % NSTAGE);
        asm volatile("cp.async.commit_group;" ::: "memory");   // may be empty

        const uint32_t st = sb + buf * STAGE;
        #pragma unroll
        for (int ks = 0; ks < 4; ++ks) {
            uint32_t ah[4][4], al[4][4], bh[2][4], bl[2][4];
            #pragma unroll
            for (int mt = 0; mt < 4; ++mt) {
                uint32_t ao = st + (uint32_t)((a_row0 + mt * 16) * 128)
                            + (uint32_t)((((ks * 2 + a_ch0) ^ a_xor)) << 4);
                ldsm4(ah[mt], ao);
                ldsm4(al[mt], ao + OFF_AL);
            }
            #pragma unroll
            for (int p = 0; p < 2; ++p) {
                uint32_t bo = st + OFF_BH + (uint32_t)((b_row0 + p * 16) * 128)
                            + (uint32_t)((((ks * 2 + b_ch0) ^ b_xor)) << 4);
                ldsm4(bh[p], bo);
                ldsm4(bl[p], bo + TILEB);
            }
            #pragma unroll
            for (int mt = 0; mt < 4; ++mt)
                #pragma unroll
                for (int nf = 0; nf < 4; ++nf)
                    mma_bf16(part[mt][nf], ah[mt], &bh[nf >> 1][(nf & 1) * 2]);
            #pragma unroll
            for (int mt = 0; mt < 4; ++mt)
                #pragma unroll
                for (int nf = 0; nf < 4; ++nf)
                    mma_bf16(part[mt][nf], ah[mt], &bl[nf >> 1][(nf & 1) * 2]);
            #pragma unroll
            for (int mt = 0; mt < 4; ++mt)
                #pragma unroll
                for (int nf = 0; nf < 4; ++nf)
                    mma_bf16(part[mt][nf], al[mt], &bh[nf >> 1][(nf & 1) * 2]);
        }

        if ((it & 7) == 7) {   // expert boundary: fold partial with w_e
            const int e = it >> 3;
            #pragma unroll
            for (int mt = 0; mt < 4; ++mt) {
                const int r0 = wm * 64 + mt * 16 + g;
                const float w0 = wsm[r0 * 8 + e];
                const float w1 = wsm[(r0 + 8) * 8 + e];
                #pragma unroll
                for (int nf = 0; nf < 4; ++nf) {
                    tot[mt][nf][0] = fmaf(w0, part[mt][nf][0], tot[mt][nf][0]);
                    tot[mt][nf][1] = fmaf(w0, part[mt][nf][1], tot[mt][nf][1]);
                    tot[mt][nf][2] = fmaf(w1, part[mt][nf][2], tot[mt][nf][2]);
                    tot[mt][nf][3] = fmaf(w1, part[mt][nf][3], tot[mt][nf][3]);
                    part[mt][nf][0] = 0.f; part[mt][nf][1] = 0.f;
                    part[mt][nf][2] = 0.f; part[mt][nf][3] = 0.f;
                }
            }
        }

        buf = (buf + 1 == NSTAGE) ? 0 : buf + 1;
    }

    // epilogue: + w @ bias, activation, store (split bf16 for MODE<2)
    #pragma unroll
    for (int mt = 0; mt < 4; ++mt) {
        const int r0 = wm * 64 + mt * 16 + g;
        float w0[8], w1[8];
        #pragma unroll
        for (int e = 0; e < 8; ++e) {
            w0[e] = wsm[r0 * 8 + e];
            w1[e] = wsm[(r0 + 8) * 8 + e];
        }
        #pragma unroll
        for (int nf = 0; nf < 4; ++nf) {
            const int c = wn * 32 + nf * 8 + t * 2;
            float b00 = 0.f, b01 = 0.f, b10 = 0.f, b11 = 0.f;
            #pragma unroll
            for (int e = 0; e < 8; ++e) {
                float be0 = bsm[e * 128 + c], be1 = bsm[e * 128 + c + 1];
                b00 = fmaf(w0[e], be0, b00); b01 = fmaf(w0[e], be1, b01);
                b10 = fmaf(w1[e], be0, b10); b11 = fmaf(w1[e], be1, b11);
            }
            float v0 = tot[mt][nf][0] + b00;
            float v1 = tot[mt][nf][1] + b01;
            float v2 = tot[mt][nf][2] + b10;
            float v3 = tot[mt][nf][3] + b11;
            if (ACT) { v0 = eluf(v0); v1 = eluf(v1); v2 = eluf(v2); v3 = eluf(v3); }
            const size_t o0 = (size_t)(mBase + r0) * DH + nBase + c;
            const size_t o1 = (size_t)(mBase + r0 + 8) * DH + nBase + c;
            if (MODE == 2) {
                *(float2*)(Yp + o0) = make_float2(v0, v1);
                *(float2*)(Yp + o1) = make_float2(v2, v3);
            } else {
                __nv_bfloat16* oh = (MODE == 0) ? g_xbh : g_xah;
                __nv_bfloat16* ol = (MODE == 0) ? g_xbl : g_xal;
                uint32_t h0, l0, h1, l1;
                splitbf2(v0, v1, h0, l0);
                splitbf2(v2, v3, h1, l1);
                *(uint32_t*)(oh + o0) = h0;
                *(uint32_t*)(ol + o0) = l0;
                *(uint32_t*)(oh + o1) = h1;
                *(uint32_t*)(ol + o1) = l1;
            }
        }
    }
}

// ---------------------------------------------------------------------------
extern "C" void kernel_launch(void* const* d_in, const int* in_sizes, int n_in,
                              void* d_out, int out_size)
{
    const float* z   = (const float*)d_in[0];
    const void*  idx = (const void*)d_in[1];
    const float* Wg1 = (const float*)d_in[2];
    const float* bg1 = (const float*)d_in[3];
    const float* Wg2 = (const float*)d_in[4];
    const float* bg2 = (const float*)d_in[5];
    const float* Wg3 = (const float*)d_in[6];
    const float* bg3 = (const float*)d_in[7];
    const float* W1  = (const float*)d_in[8];
    const float* b1  = (const float*)d_in[9];
    const float* W2  = (const float*)d_in[10];
    const float* b2  = (const float*)d_in[11];
    const float* W3  = (const float*)d_in[12];
    const float* b3  = (const float*)d_in[13];
    float* out = (float*)d_out;

    cudaFuncSetAttribute(layer_mm<true , 0>, cudaFuncAttributeMaxDynamicSharedMemorySize, SMEM_BYTES);
    cudaFuncSetAttribute(layer_mm<true , 1>, cudaFuncAttributeMaxDynamicSharedMemorySize, SMEM_BYTES);
    cudaFuncSetAttribute(layer_mm<false, 2>, cudaFuncAttributeMaxDynamicSharedMemorySize, SMEM_BYTES);

    splitz_kernel<<<(BATCH * DIN / 4 + 255) / 256, 256>>>(z);

    dim3 wgrid(KTOT / 32, DH / 32);   // (128, 16)
    dim3 wblk(32, 8);
    wsplit_kernel<<<wgrid, wblk>>>(W1, 0);
    wsplit_kernel<<<wgrid, wblk>>>(W2, 1);
    wsplit_kernel<<<wgrid, wblk>>>(W3, 2);

    gating_kernel<<<1024, 256>>>(z, idx, Wg1, bg1, Wg2, bg2, Wg3, bg3);

    dim3 grid(DH / BN, BATCH / BM);   // (4, 512)
    layer_mm<true , 0><<<grid, NTHR, SMEM_BYTES>>>(b1, nullptr);
    layer_mm<true , 1><<<grid, NTHR, SMEM_BYTES>>>(b2, nullptr);
    layer_mm<false, 2><<<grid, NTHR, SMEM_BYTES>>>(b3, out);
}